// round 8
// baseline (speedup 1.0000x reference)
#include <cuda_runtime.h>
#include <cstdint>

#define N_NODES 50000
#define N_EDGES 1600000
#define DIM 128
#define NH 8
#define TILE_E 64
#define NTILES (N_EDGES / TILE_E)   // 25000
#define NPER 152                    // persistent CTAs (1 per SM)
#define PAD 132                     // padded row stride (words) for SMEM tiles

// ---------------- scratch (static device globals: no alloc allowed) ----------
__device__ float g_Q[(size_t)N_NODES * DIM];
__device__ float g_K[(size_t)N_NODES * DIM];
__device__ float g_V[(size_t)N_NODES * DIM];
__device__ int   g_cnt[N_NODES];
__device__ int   g_base[N_NODES + 1];
__device__ int   g_psrc[N_EDGES];     // slot -> src node
__device__ int   g_pdst[N_EDGES];     // slot -> dst node
__device__ int   g_pinv[N_EDGES];     // slot -> original edge id
__device__ float g_pscore[(size_t)N_EDGES * NH];   // 51 MB
__device__ int   g_idx64;

// ---------------- edge_index dtype detection (int64 vs int32) ----------------
__global__ void detect_idx_kernel(const void* idx) {
    const long long* p = (const long long*)idx;
    int is64 = 1;
    for (int i = 0; i < 64; i++) {
        long long v = p[i];
        if (v < 0 || v >= N_NODES) { is64 = 0; break; }
    }
    g_idx64 = is64;
}

// ---------------- histogram of dst --------------------------------------------
__global__ __launch_bounds__(256)
void hist_kernel(const void* __restrict__ eidx, int* __restrict__ cnt) {
    const int i = blockIdx.x * blockDim.x + threadIdx.x;
    if (i >= N_EDGES) return;
    int dst;
    if (g_idx64) dst = (int)((const long long*)eidx)[(size_t)N_EDGES + i];
    else         dst = ((const int*)eidx)[N_EDGES + i];
    atomicAdd(&cnt[dst], 1);
}

// ---------------- single-block exclusive scan (1024 threads) ------------------
__global__ __launch_bounds__(1024)
void scan_kernel(const int* __restrict__ cnt, int* __restrict__ base) {
    __shared__ int wsum[32];
    const int tid = threadIdx.x;
    const int lane = tid & 31, wid = tid >> 5;
    const int CH = (N_NODES + 1023) / 1024;   // 49
    const int start = tid * CH;

    int s = 0;
    for (int i = 0; i < CH; i++) {
        const int idx = start + i;
        if (idx < N_NODES) s += cnt[idx];
    }
    int v = s;
#pragma unroll
    for (int d = 1; d < 32; d <<= 1) {
        int n = __shfl_up_sync(0xffffffffu, v, d);
        if (lane >= d) v += n;
    }
    if (lane == 31) wsum[wid] = v;
    __syncthreads();
    if (wid == 0) {
        int wv = wsum[lane];
#pragma unroll
        for (int d = 1; d < 32; d <<= 1) {
            int n = __shfl_up_sync(0xffffffffu, wv, d);
            if (lane >= d) wv += n;
        }
        wsum[lane] = wv;
    }
    __syncthreads();
    int run = v - s + (wid > 0 ? wsum[wid - 1] : 0);
    for (int i = 0; i < CH; i++) {
        const int idx = start + i;
        if (idx < N_NODES) { base[idx] = run; run += cnt[idx]; }
    }
    if (tid == 1023) base[N_NODES] = run;
}

// ---------------- convert: CSR slot assignment + permutation arrays ----------
__global__ __launch_bounds__(256)
void convert_kernel(const void* __restrict__ eidx,
                    const int* __restrict__ base, int* __restrict__ cnt,
                    int* __restrict__ psrc, int* __restrict__ pdst,
                    int* __restrict__ pinv) {
    const int i = blockIdx.x * blockDim.x + threadIdx.x;
    if (i >= N_EDGES) return;
    int s, d;
    if (g_idx64) {
        const long long* p = (const long long*)eidx;
        s = (int)p[i];
        d = (int)p[(size_t)N_EDGES + i];
    } else {
        const int* p = (const int*)eidx;
        s = p[i];
        d = p[N_EDGES + i];
    }
    const int pp = base[d] + atomicAdd(&cnt[d], 1);
    psrc[pp] = s;
    pdst[pp] = d;
    pinv[pp] = i;
}

// ---------------- node projections: 3 GEMMs in one launch (gridDim.y) ---------
#define BM 64
#define BK 16

__global__ __launch_bounds__(256)
void sgemm3_kernel(const float* __restrict__ A,
                   const float* __restrict__ WQ, const float* __restrict__ WK,
                   const float* __restrict__ WV,
                   float* __restrict__ Q, float* __restrict__ K,
                   float* __restrict__ V, int M) {
    const float* W = (blockIdx.y == 0) ? WQ : (blockIdx.y == 1) ? WK : WV;
    float*       C = (blockIdx.y == 0) ? Q  : (blockIdx.y == 1) ? K  : V;

    __shared__ float As[BK][BM + 1];
    __shared__ float Ws[BK][DIM];

    const int tid = threadIdx.x;
    const int tx = tid & 31;
    const int ty = tid >> 5;
    const int m0 = blockIdx.x * BM;

    float acc[8][4];
#pragma unroll
    for (int i = 0; i < 8; i++)
#pragma unroll
        for (int j = 0; j < 4; j++) acc[i][j] = 0.0f;

    for (int k0 = 0; k0 < DIM; k0 += BK) {
        {
            const int r = tid >> 2;
            const int c = (tid & 3) * 4;
            const int gr = m0 + r;
            float4 a = make_float4(0.f, 0.f, 0.f, 0.f);
            if (gr < M) a = *(const float4*)(A + (size_t)gr * DIM + k0 + c);
            As[c + 0][r] = a.x;
            As[c + 1][r] = a.y;
            As[c + 2][r] = a.z;
            As[c + 3][r] = a.w;
        }
        {
            const int cw = (tid & 31) * 4;
            const int rw = tid >> 5;
            *(float4*)&Ws[rw][cw]     = *(const float4*)(W + (size_t)(k0 + rw) * DIM + cw);
            *(float4*)&Ws[rw + 8][cw] = *(const float4*)(W + (size_t)(k0 + rw + 8) * DIM + cw);
        }
        __syncthreads();

#pragma unroll
        for (int kk = 0; kk < BK; kk++) {
            float a[8];
#pragma unroll
            for (int i = 0; i < 8; i++) a[i] = As[kk][ty * 8 + i];
            const float4 wv = *(const float4*)&Ws[kk][tx * 4];
#pragma unroll
            for (int i = 0; i < 8; i++) {
                acc[i][0] = fmaf(a[i], wv.x, acc[i][0]);
                acc[i][1] = fmaf(a[i], wv.y, acc[i][1]);
                acc[i][2] = fmaf(a[i], wv.z, acc[i][2]);
                acc[i][3] = fmaf(a[i], wv.w, acc[i][3]);
            }
        }
        __syncthreads();
    }

#pragma unroll
    for (int i = 0; i < 8; i++) {
        const int gr = m0 + ty * 8 + i;
        if (gr < M) {
            *(float4*)(C + (size_t)gr * DIM + tx * 4) =
                make_float4(acc[i][0], acc[i][1], acc[i][2], acc[i][3]);
        }
    }
}

// ---------------- tf32 helpers -----------------------------------------------
__device__ __forceinline__ uint32_t f2tf(float f) {
    uint32_t u;
    asm("cvt.rna.tf32.f32 %0, %1;" : "=r"(u) : "f"(f));
    return u;
}

__device__ __forceinline__ void mma_tf32(float* d, const uint32_t* a, const uint32_t* b) {
    asm volatile(
        "mma.sync.aligned.m16n8k8.row.col.f32.tf32.tf32.f32 "
        "{%0,%1,%2,%3}, {%4,%5,%6,%7}, {%8,%9}, {%0,%1,%2,%3};"
        : "+f"(d[0]), "+f"(d[1]), "+f"(d[2]), "+f"(d[3])
        : "r"(a[0]), "r"(a[1]), "r"(a[2]), "r"(a[3]),
          "r"(b[0]), "r"(b[1]));
}

// named barriers (count = 384 = 128 compute + 256 memory threads)
#define NBAR 384
#define BAR_ARRIVE(id) asm volatile("bar.arrive %0, %1;" :: "r"(id), "r"(NBAR) : "memory")
#define BAR_SYNC(id)   asm volatile("bar.sync %0, %1;"   :: "r"(id), "r"(NBAR) : "memory")
// ids: A_FULL = 1+b, A_EMPTY = 3+b, EH_FULL = 5+b, EH_EMPTY = 7+b

// ---------------- fused edge kernel: warp-specialized producer/consumer -------
// 1 CTA/SM, 384 threads. Warps 0-3: GEMM only (SMEM->mma->Eh). Warps 4-11:
// A-tile gather/convert/STS for tile j AND score epilogue of tile j-1.
// Double-buffered A (tf32) and Eh (fp32); handoff via named barriers so the
// mma pipe never waits on LDG/L2 latency.
__global__ __launch_bounds__(384, 1)
void fused_edge_kernel(const float* __restrict__ ea,
                       const float* __restrict__ WE,
                       const float* __restrict__ Q,
                       const float* __restrict__ K,
                       const int* __restrict__ psrc,
                       const int* __restrict__ pdst,
                       const int* __restrict__ pinv,
                       float* __restrict__ pscore) {
    extern __shared__ float smem[];
    uint32_t* Wsu = (uint32_t*)smem;                    // 128*PAD
    uint32_t* Ab[2];
    Ab[0] = (uint32_t*)(smem + 128 * PAD);              // 64*PAD each
    Ab[1] = Ab[0] + TILE_E * PAD;
    float* Ehb[2];
    Ehb[0] = (float*)(Ab[1] + TILE_E * PAD);
    Ehb[1] = Ehb[0] + TILE_E * PAD;

    const int tid  = threadIdx.x;
    const int lane = tid & 31;
    const int w    = tid >> 5;                          // 0..11

    // ---- load WE (128x128) into SMEM as tf32, all threads ----
    for (int idx = tid; idx < 4096; idx += 384) {
        const int r  = idx >> 5;
        const int c4 = (idx & 31) << 2;
        float4 wv = *(const float4*)(WE + (size_t)r * DIM + c4);
        *(uint4*)&Wsu[r * PAD + c4] =
            make_uint4(f2tf(wv.x), f2tf(wv.y), f2tf(wv.z), f2tf(wv.w));
    }
    __syncthreads();

    const int cnt = 164 + (blockIdx.x < (NTILES - NPER * 164) ? 1 : 0);

    if (w < 4) {
        // ================= COMPUTE warps (0-3): 32M x 64N tiles =================
        const int g  = lane >> 2;
        const int cc = lane & 3;
        const int mb = (w & 1) * 32;
        const int nb = (w >> 1) * 64;

        for (int j = 0; j < cnt; j++) {
            const int b = j & 1;
            BAR_SYNC(1 + b);                 // A[j] loaded
            if (j >= 2) BAR_SYNC(7 + b);     // Eh buffer free (epilogue j-2 done)

            const uint32_t* Asu = Ab[b];
            float acc[2][8][4];
#pragma unroll
            for (int mt = 0; mt < 2; mt++)
#pragma unroll
                for (int nt = 0; nt < 8; nt++)
#pragma unroll
                    for (int q = 0; q < 4; q++) acc[mt][nt][q] = 0.0f;

#pragma unroll
            for (int ks = 0; ks < 16; ks++) {
                const int kc = 8 * ks + cc;
                uint32_t a[2][4];
#pragma unroll
                for (int mt = 0; mt < 2; mt++) {
                    const int r = mb + 16 * mt + g;
                    a[mt][0] = Asu[r * PAD + kc];
                    a[mt][1] = Asu[(r + 8) * PAD + kc];
                    a[mt][2] = Asu[r * PAD + kc + 4];
                    a[mt][3] = Asu[(r + 8) * PAD + kc + 4];
                }
                uint32_t bfr[8][2];
#pragma unroll
                for (int nt = 0; nt < 8; nt++) {
                    const int n = nb + 8 * nt + g;
                    bfr[nt][0] = Wsu[kc * PAD + n];
                    bfr[nt][1] = Wsu[(kc + 4) * PAD + n];
                }
#pragma unroll
                for (int mt = 0; mt < 2; mt++)
#pragma unroll
                    for (int nt = 0; nt < 8; nt++)
                        mma_tf32(acc[mt][nt], a[mt], bfr[nt]);
            }

            // write Eh tile
            float* Eh = Ehb[b];
#pragma unroll
            for (int mt = 0; mt < 2; mt++) {
#pragma unroll
                for (int nt = 0; nt < 8; nt++) {
                    const int r   = mb + 16 * mt + g;
                    const int col = nb + 8 * nt + 2 * cc;
                    *(float2*)&Eh[r * PAD + col] =
                        make_float2(acc[mt][nt][0], acc[mt][nt][1]);
                    *(float2*)&Eh[(r + 8) * PAD + col] =
                        make_float2(acc[mt][nt][2], acc[mt][nt][3]);
                }
            }
            BAR_ARRIVE(5 + b);   // Eh[j] full
            BAR_ARRIVE(3 + b);   // A[j] consumed
        }
    } else {
        // ================= MEMORY warps (4-11): A-load + epilogue ===============
        const int wl = w - 4;    // 0..7

        for (int j = 0; j <= cnt; j++) {
            // ---- load A(tile j) into Ab[j&1] ----
            if (j < cnt) {
                const int b = j & 1;
                if (j >= 2) BAR_SYNC(3 + b);      // buffer free
                const int tile = blockIdx.x + j * NPER;
                const int e0 = tile * TILE_E;
                int myp = 0;
                if (lane < 8) myp = __ldg(pinv + e0 + wl + 8 * lane);
                uint32_t* Adst = Ab[b];
#pragma unroll
                for (int i = 0; i < 8; i++) {
                    const int eid = __shfl_sync(0xffffffffu, myp, i);
                    const int r   = wl + 8 * i;
                    const float4 av = __ldg((const float4*)(ea + (size_t)eid * DIM) + lane);
                    *(uint4*)&Adst[r * PAD + lane * 4] =
                        make_uint4(f2tf(av.x), f2tf(av.y), f2tf(av.z), f2tf(av.w));
                }
                BAR_ARRIVE(1 + b);                // A[j] full
            }
            // ---- epilogue of tile j-1 ----
            if (j >= 1) {
                const int b = (j - 1) & 1;
                BAR_SYNC(5 + b);                  // Eh[j-1] full
                const int tile = blockIdx.x + (j - 1) * NPER;
                const int e0 = tile * TILE_E;
                const float* Eh = Ehb[b];
#pragma unroll 1
                for (int b0 = 0; b0 < 8; b0 += 4) {
                    int src[4];
                    float4 ehv[4], kv[4], qv[4];
#pragma unroll
                    for (int jj = 0; jj < 4; jj++) {
                        const int el   = wl * 8 + b0 + jj;
                        const int slot = e0 + el;
                        src[jj] = __ldg(psrc + slot);
                        const int dst = __ldg(pdst + slot);
                        ehv[jj] = *(const float4*)&Eh[el * PAD + 4 * lane];
                        kv[jj]  = __ldg((const float4*)(K + (size_t)src[jj] * DIM) + lane);
                        qv[jj]  = __ldg((const float4*)(Q + (size_t)dst * DIM) + lane);
                    }
#pragma unroll
                    for (int jj = 0; jj < 4; jj++) {
                        float s = ehv[jj].x * kv[jj].x * qv[jj].x +
                                  ehv[jj].y * kv[jj].y * qv[jj].y +
                                  ehv[jj].z * kv[jj].z * qv[jj].z +
                                  ehv[jj].w * kv[jj].w * qv[jj].w;
                        s += __shfl_xor_sync(0xffffffffu, s, 1);
                        s += __shfl_xor_sync(0xffffffffu, s, 2);
                        s *= 0.25f;
                        s = expf(fminf(fmaxf(s, -5.0f), 5.0f));
                        if ((lane & 3) == 0)
                            pscore[(size_t)(e0 + wl * 8 + b0 + jj) * NH + (lane >> 2)] = s;
                    }
                }
                BAR_ARRIVE(7 + b);                // Eh[j-1] consumed
            }
        }
    }
}

// ---------------- gather: one warp per node, register accumulation ------------
__global__ __launch_bounds__(256)
void gather_kernel(const int* __restrict__ base,
                   const int* __restrict__ psrc,
                   const float* __restrict__ pscore,
                   const float* __restrict__ V,
                   float* __restrict__ out) {
    const int node = (blockIdx.x * blockDim.x + threadIdx.x) >> 5;
    const int lane = threadIdx.x & 31;
    if (node >= N_NODES) return;

    const int b = base[node];
    const int e = base[node + 1];
    const int h = lane >> 2;

    float4 acc = make_float4(0.f, 0.f, 0.f, 0.f);
    float z = 0.f;

    for (int cb = b; cb < e; cb += 32) {
        const int n = min(32, e - cb);
        int mysrc = 0;
        if (cb + lane < e) mysrc = __ldg(psrc + cb + lane);

        int i = 0;
        for (; i + 8 <= n; i += 8) {
#pragma unroll
            for (int u = 0; u < 8; u++) {
                const int src = __shfl_sync(0xffffffffu, mysrc, i + u);
                const float s = __ldg(pscore + (size_t)(cb + i + u) * NH + h);
                const float4 v = __ldg((const float4*)(V + (size_t)src * DIM) + lane);
                acc.x = fmaf(v.x, s, acc.x);
                acc.y = fmaf(v.y, s, acc.y);
                acc.z = fmaf(v.z, s, acc.z);
                acc.w = fmaf(v.w, s, acc.w);
                z += s;
            }
        }
        for (; i < n; i++) {
            const int src = __shfl_sync(0xffffffffu, mysrc, i);
            const float s = __ldg(pscore + (size_t)(cb + i) * NH + h);
            const float4 v = __ldg((const float4*)(V + (size_t)src * DIM) + lane);
            acc.x = fmaf(v.x, s, acc.x);
            acc.y = fmaf(v.y, s, acc.y);
            acc.z = fmaf(v.z, s, acc.z);
            acc.w = fmaf(v.w, s, acc.w);
            z += s;
        }
    }
    const float inv = 1.0f / (z + 1e-6f);
    *(float4*)(out + (size_t)node * DIM + lane * 4) =
        make_float4(acc.x * inv, acc.y * inv, acc.z * inv, acc.w * inv);
}

// ---------------- launch --------------------------------------------------------
extern "C" void kernel_launch(void* const* d_in, const int* in_sizes, int n_in,
                              void* d_out, int out_size) {
    const float* h   = (const float*)d_in[0];
    const float* ea  = (const float*)d_in[1];
    const float* WQ  = (const float*)d_in[2];
    const float* WK  = (const float*)d_in[3];
    const float* WV  = (const float*)d_in[4];
    const float* WE  = (const float*)d_in[5];
    const void*  eix = d_in[6];
    float* out = (float*)d_out;

    void *qp, *kp, *vp, *cntp, *basep, *psrcp, *pdstp, *pinvp, *pscorep;
    cudaGetSymbolAddress(&qp,      g_Q);
    cudaGetSymbolAddress(&kp,      g_K);
    cudaGetSymbolAddress(&vp,      g_V);
    cudaGetSymbolAddress(&cntp,    g_cnt);
    cudaGetSymbolAddress(&basep,   g_base);
    cudaGetSymbolAddress(&psrcp,   g_psrc);
    cudaGetSymbolAddress(&pdstp,   g_pdst);
    cudaGetSymbolAddress(&pinvp,   g_pinv);
    cudaGetSymbolAddress(&pscorep, g_pscore);

    detect_idx_kernel<<<1, 1>>>(eix);

    // CSR build
    cudaMemsetAsync(cntp, 0, N_NODES * sizeof(int));
    hist_kernel<<<(N_EDGES + 255) / 256, 256>>>(eix, (int*)cntp);
    scan_kernel<<<1, 1024>>>((const int*)cntp, (int*)basep);
    cudaMemsetAsync(cntp, 0, N_NODES * sizeof(int));
    convert_kernel<<<(N_EDGES + 255) / 256, 256>>>(
        eix, (const int*)basep, (int*)cntp,
        (int*)psrcp, (int*)pdstp, (int*)pinvp);

    // node projections (3 GEMMs in one launch)
    dim3 gN((N_NODES + BM - 1) / BM, 3);
    sgemm3_kernel<<<gN, 256>>>(h, WQ, WK, WV, (float*)qp, (float*)kp, (float*)vp,
                               N_NODES);

    // fused persistent warp-specialized edge GEMM + score
    const int smem_bytes = (128 + 4 * TILE_E) * PAD * sizeof(float);   // 202752
    cudaFuncSetAttribute(fused_edge_kernel,
                         cudaFuncAttributeMaxDynamicSharedMemorySize, smem_bytes);
    fused_edge_kernel<<<NPER, 384, smem_bytes>>>(
        ea, WE, (const float*)qp, (const float*)kp,
        (const int*)psrcp, (const int*)pdstp, (const int*)pinvp,
        (float*)pscorep);

    // gather + normalize (one warp per node)
    gather_kernel<<<(N_NODES * 32 + 255) / 256, 256>>>(
        (const int*)basep, (const int*)psrcp, (const float*)pscorep,
        (const float*)vp, out);
}

// round 9
// speedup vs baseline: 1.4961x; 1.4961x over previous
#include <cuda_runtime.h>
#include <cuda_fp16.h>
#include <cstdint>

#define N_NODES 50000
#define N_EDGES 1600000
#define DIM 128
#define NH 8
#define TILE_E 64
#define NTILES (N_EDGES / TILE_E)   // 25000
#define NPER 304                    // persistent CTAs (2 per SM x 152 SMs)
#define PAD 132                     // Eh row stride (floats)
#define PADA 68                     // A tile row stride (half2 units)
#define PADB 136                    // B tile row stride (half2 units)

// ---------------- scratch (static device globals: no alloc allowed) ----------
__device__ float g_Q[(size_t)N_NODES * DIM];
__device__ float g_K[(size_t)N_NODES * DIM];
__device__ float g_V[(size_t)N_NODES * DIM];
__device__ int   g_cnt[N_NODES];
__device__ int   g_base[N_NODES + 1];
__device__ int   g_psrc[N_EDGES];     // slot -> src node
__device__ int   g_pdst[N_EDGES];     // slot -> dst node
__device__ int   g_pinv[N_EDGES];     // slot -> original edge id
__device__ float g_pscore[(size_t)N_EDGES * NH];   // 51 MB
__device__ int   g_idx64;

// ---------------- edge_index dtype detection (int64 vs int32) ----------------
__global__ void detect_idx_kernel(const void* idx) {
    const long long* p = (const long long*)idx;
    int is64 = 1;
    for (int i = 0; i < 64; i++) {
        long long v = p[i];
        if (v < 0 || v >= N_NODES) { is64 = 0; break; }
    }
    g_idx64 = is64;
}

// ---------------- histogram of dst --------------------------------------------
__global__ __launch_bounds__(256)
void hist_kernel(const void* __restrict__ eidx, int* __restrict__ cnt) {
    const int i = blockIdx.x * blockDim.x + threadIdx.x;
    if (i >= N_EDGES) return;
    int dst;
    if (g_idx64) dst = (int)((const long long*)eidx)[(size_t)N_EDGES + i];
    else         dst = ((const int*)eidx)[N_EDGES + i];
    atomicAdd(&cnt[dst], 1);
}

// ---------------- single-block exclusive scan (1024 threads) ------------------
__global__ __launch_bounds__(1024)
void scan_kernel(const int* __restrict__ cnt, int* __restrict__ base) {
    __shared__ int wsum[32];
    const int tid = threadIdx.x;
    const int lane = tid & 31, wid = tid >> 5;
    const int CH = (N_NODES + 1023) / 1024;   // 49
    const int start = tid * CH;

    int s = 0;
    for (int i = 0; i < CH; i++) {
        const int idx = start + i;
        if (idx < N_NODES) s += cnt[idx];
    }
    int v = s;
#pragma unroll
    for (int d = 1; d < 32; d <<= 1) {
        int n = __shfl_up_sync(0xffffffffu, v, d);
        if (lane >= d) v += n;
    }
    if (lane == 31) wsum[wid] = v;
    __syncthreads();
    if (wid == 0) {
        int wv = wsum[lane];
#pragma unroll
        for (int d = 1; d < 32; d <<= 1) {
            int n = __shfl_up_sync(0xffffffffu, wv, d);
            if (lane >= d) wv += n;
        }
        wsum[lane] = wv;
    }
    __syncthreads();
    int run = v - s + (wid > 0 ? wsum[wid - 1] : 0);
    for (int i = 0; i < CH; i++) {
        const int idx = start + i;
        if (idx < N_NODES) { base[idx] = run; run += cnt[idx]; }
    }
    if (tid == 1023) base[N_NODES] = run;
}

// ---------------- convert: CSR slot assignment + permutation arrays ----------
__global__ __launch_bounds__(256)
void convert_kernel(const void* __restrict__ eidx,
                    const int* __restrict__ base, int* __restrict__ cnt,
                    int* __restrict__ psrc, int* __restrict__ pdst,
                    int* __restrict__ pinv) {
    const int i = blockIdx.x * blockDim.x + threadIdx.x;
    if (i >= N_EDGES) return;
    int s, d;
    if (g_idx64) {
        const long long* p = (const long long*)eidx;
        s = (int)p[i];
        d = (int)p[(size_t)N_EDGES + i];
    } else {
        const int* p = (const int*)eidx;
        s = p[i];
        d = p[N_EDGES + i];
    }
    const int pp = base[d] + atomicAdd(&cnt[d], 1);
    psrc[pp] = s;
    pdst[pp] = d;
    pinv[pp] = i;
}

// ---------------- node projections: 3 GEMMs in one launch (gridDim.y) ---------
#define BM 64
#define BK 16

__global__ __launch_bounds__(256)
void sgemm3_kernel(const float* __restrict__ A,
                   const float* __restrict__ WQ, const float* __restrict__ WK,
                   const float* __restrict__ WV,
                   float* __restrict__ Q, float* __restrict__ K,
                   float* __restrict__ V, int M) {
    const float* W = (blockIdx.y == 0) ? WQ : (blockIdx.y == 1) ? WK : WV;
    float*       C = (blockIdx.y == 0) ? Q  : (blockIdx.y == 1) ? K  : V;

    __shared__ float As[BK][BM + 1];
    __shared__ float Ws[BK][DIM];

    const int tid = threadIdx.x;
    const int tx = tid & 31;
    const int ty = tid >> 5;
    const int m0 = blockIdx.x * BM;

    float acc[8][4];
#pragma unroll
    for (int i = 0; i < 8; i++)
#pragma unroll
        for (int j = 0; j < 4; j++) acc[i][j] = 0.0f;

    for (int k0 = 0; k0 < DIM; k0 += BK) {
        {
            const int r = tid >> 2;
            const int c = (tid & 3) * 4;
            const int gr = m0 + r;
            float4 a = make_float4(0.f, 0.f, 0.f, 0.f);
            if (gr < M) a = *(const float4*)(A + (size_t)gr * DIM + k0 + c);
            As[c + 0][r] = a.x;
            As[c + 1][r] = a.y;
            As[c + 2][r] = a.z;
            As[c + 3][r] = a.w;
        }
        {
            const int cw = (tid & 31) * 4;
            const int rw = tid >> 5;
            *(float4*)&Ws[rw][cw]     = *(const float4*)(W + (size_t)(k0 + rw) * DIM + cw);
            *(float4*)&Ws[rw + 8][cw] = *(const float4*)(W + (size_t)(k0 + rw + 8) * DIM + cw);
        }
        __syncthreads();

#pragma unroll
        for (int kk = 0; kk < BK; kk++) {
            float a[8];
#pragma unroll
            for (int i = 0; i < 8; i++) a[i] = As[kk][ty * 8 + i];
            const float4 wv = *(const float4*)&Ws[kk][tx * 4];
#pragma unroll
            for (int i = 0; i < 8; i++) {
                acc[i][0] = fmaf(a[i], wv.x, acc[i][0]);
                acc[i][1] = fmaf(a[i], wv.y, acc[i][1]);
                acc[i][2] = fmaf(a[i], wv.z, acc[i][2]);
                acc[i][3] = fmaf(a[i], wv.w, acc[i][3]);
            }
        }
        __syncthreads();
    }

#pragma unroll
    for (int i = 0; i < 8; i++) {
        const int gr = m0 + ty * 8 + i;
        if (gr < M) {
            *(float4*)(C + (size_t)gr * DIM + tx * 4) =
                make_float4(acc[i][0], acc[i][1], acc[i][2], acc[i][3]);
        }
    }
}

// ---------------- fp16 helpers -------------------------------------------------
__device__ __forceinline__ uint32_t f2h2(float lo, float hi) {
    __half2 h = __floats2half2_rn(lo, hi);
    return *(uint32_t*)&h;
}

__device__ __forceinline__ void mma_f16(float* d, const uint32_t* a, const uint32_t* b) {
    asm volatile(
        "mma.sync.aligned.m16n8k16.row.col.f32.f16.f16.f32 "
        "{%0,%1,%2,%3}, {%4,%5,%6,%7}, {%8,%9}, {%0,%1,%2,%3};"
        : "+f"(d[0]), "+f"(d[1]), "+f"(d[2]), "+f"(d[3])
        : "r"(a[0]), "r"(a[1]), "r"(a[2]), "r"(a[3]),
          "r"(b[0]), "r"(b[1]));
}

// ---------------- fused edge kernel: persistent, prefetch-pipelined, fp16 -----
// Grid = 304 persistent CTAs (2/SM). Each CTA: load WE once as half2 into SMEM;
// per tile of 64 slots: STS prefetched ea rows (half2) -> fp16 m16n8k16 GEMM
// (prefetching next tile's ea rows) -> Eh (fp32) to SMEM -> score epilogue.
// SMEM: B2 64x136 h2 (34.8KB) + A2 64x68 h2 (17.4KB) + Eh 64x132 f32 (33.8KB).
__global__ __launch_bounds__(256, 2)
void fused_edge_kernel(const float* __restrict__ ea,
                       const float* __restrict__ WE,
                       const float* __restrict__ Q,
                       const float* __restrict__ K,
                       const int* __restrict__ psrc,
                       const int* __restrict__ pdst,
                       const int* __restrict__ pinv,
                       float* __restrict__ pscore) {
    extern __shared__ uint32_t smem[];
    uint32_t* B2 = smem;                         // [64][PADB] half2
    uint32_t* A2 = B2 + 64 * PADB;               // [64][PADA] half2
    float*    Eh = (float*)(A2 + 64 * PADA);     // [64][PAD]  fp32

    const int tid  = threadIdx.x;
    const int lane = tid & 31;
    const int w    = tid >> 5;                   // 0..7

    // ---- load WE (128x128) into SMEM as half2 along k — ONCE per CTA ----
    // B2[kk][n] = half2(WE[2kk][n], WE[2kk+1][n]); consecutive tid -> consecutive n.
    for (int idx = tid; idx < 64 * DIM; idx += 256) {
        const int kk = idx >> 7;
        const int n  = idx & 127;
        const float w0 = __ldg(WE + (size_t)(2 * kk) * DIM + n);
        const float w1 = __ldg(WE + (size_t)(2 * kk + 1) * DIM + n);
        B2[kk * PADB + n] = f2h2(w0, w1);
    }

    const int cnt = 82 + (blockIdx.x < (NTILES - NPER * 82) ? 1 : 0);

    // ---- register prefetch of one A tile (warp w owns rows w, w+8, .., w+56)
    float4 areg[8];
    auto prefetchA = [&](int tile) {
        const int e0 = tile * TILE_E;
        int myp = 0;
        if (lane < 8) myp = __ldg(pinv + e0 + w + 8 * lane);
#pragma unroll
        for (int i = 0; i < 8; i++) {
            const int eid = __shfl_sync(0xffffffffu, myp, i);
            areg[i] = __ldg((const float4*)(ea + (size_t)eid * DIM) + lane);
        }
    };

    prefetchA(blockIdx.x);   // prologue

    const int g  = lane >> 2;
    const int cc = lane & 3;
    const int mb = (w & 1) * 32;
    const int nb = (w >> 1) * 32;

    for (int j = 0; j < cnt; j++) {
        const int tile = blockIdx.x + j * NPER;
        const int e0   = tile * TILE_E;

        __syncthreads();   // previous epilogue done reading Eh

        // ---- STS prefetched rows as half2 (k pairs) ----
#pragma unroll
        for (int i = 0; i < 8; i++) {
            const int r = w + 8 * i;
            A2[r * PADA + lane * 2]     = f2h2(areg[i].x, areg[i].y);
            A2[r * PADA + lane * 2 + 1] = f2h2(areg[i].z, areg[i].w);
        }
        __syncthreads();

        // ---- prefetch next tile's A rows (LDGs hide under the GEMM below) ----
        if (j + 1 < cnt) prefetchA(blockIdx.x + (j + 1) * NPER);

        // ---- GEMM: 8 warps, each 32 slots x 32 cols, fp16 m16n8k16 ----
        float acc[2][4][4];
#pragma unroll
        for (int mt = 0; mt < 2; mt++)
#pragma unroll
            for (int nt = 0; nt < 4; nt++)
#pragma unroll
                for (int q = 0; q < 4; q++) acc[mt][nt][q] = 0.0f;

#pragma unroll
        for (int ks = 0; ks < 8; ks++) {
            const int kk = 8 * ks + cc;            // half2 index along k
            uint32_t a[2][4];
#pragma unroll
            for (int mt = 0; mt < 2; mt++) {
                const int r = mb + 16 * mt + g;
                a[mt][0] = A2[r * PADA + kk];
                a[mt][1] = A2[(r + 8) * PADA + kk];
                a[mt][2] = A2[r * PADA + kk + 4];
                a[mt][3] = A2[(r + 8) * PADA + kk + 4];
            }
            uint32_t b[4][2];
#pragma unroll
            for (int nt = 0; nt < 4; nt++) {
                const int n = nb + 8 * nt + g;
                b[nt][0] = B2[kk * PADB + n];
                b[nt][1] = B2[(kk + 4) * PADB + n];
            }
#pragma unroll
            for (int mt = 0; mt < 2; mt++)
#pragma unroll
                for (int nt = 0; nt < 4; nt++)
                    mma_f16(acc[mt][nt], a[mt], b[nt]);
        }
        __syncthreads();   // everyone done READING A2 (epilogue may alias? no — separate Eh)

        // ---- write Eh tile (fp32) ----
#pragma unroll
        for (int mt = 0; mt < 2; mt++) {
#pragma unroll
            for (int nt = 0; nt < 4; nt++) {
                const int r   = mb + 16 * mt + g;
                const int col = nb + 8 * nt + 2 * cc;
                *(float2*)&Eh[r * PAD + col] =
                    make_float2(acc[mt][nt][0], acc[mt][nt][1]);
                *(float2*)&Eh[(r + 8) * PAD + col] =
                    make_float2(acc[mt][nt][2], acc[mt][nt][3]);
            }
        }
        __syncthreads();

        // ---- score + sequential slot write: warp w handles slots 8w..8w+7 ----
#pragma unroll 1
        for (int b0 = 0; b0 < 8; b0 += 4) {
            int src[4];
            float4 ehv[4], kv[4], qv[4];
#pragma unroll
            for (int jj = 0; jj < 4; jj++) {
                const int el   = w * 8 + b0 + jj;
                const int slot = e0 + el;
                src[jj] = __ldg(psrc + slot);
                const int dst = __ldg(pdst + slot);
                ehv[jj] = *(const float4*)&Eh[el * PAD + 4 * lane];
                kv[jj]  = __ldg((const float4*)(K + (size_t)src[jj] * DIM) + lane);
                qv[jj]  = __ldg((const float4*)(Q + (size_t)dst * DIM) + lane);
            }
#pragma unroll
            for (int jj = 0; jj < 4; jj++) {
                float s = ehv[jj].x * kv[jj].x * qv[jj].x +
                          ehv[jj].y * kv[jj].y * qv[jj].y +
                          ehv[jj].z * kv[jj].z * qv[jj].z +
                          ehv[jj].w * kv[jj].w * qv[jj].w;
                s += __shfl_xor_sync(0xffffffffu, s, 1);
                s += __shfl_xor_sync(0xffffffffu, s, 2);
                s *= 0.25f;
                s = expf(fminf(fmaxf(s, -5.0f), 5.0f));
                if ((lane & 3) == 0)
                    pscore[(size_t)(e0 + w * 8 + b0 + jj) * NH + (lane >> 2)] = s;
            }
        }
    }
}

// ---------------- gather: one warp per node, register accumulation ------------
__global__ __launch_bounds__(256)
void gather_kernel(const int* __restrict__ base,
                   const int* __restrict__ psrc,
                   const float* __restrict__ pscore,
                   const float* __restrict__ V,
                   float* __restrict__ out) {
    const int node = (blockIdx.x * blockDim.x + threadIdx.x) >> 5;
    const int lane = threadIdx.x & 31;
    if (node >= N_NODES) return;

    const int b = base[node];
    const int e = base[node + 1];
    const int h = lane >> 2;

    float4 acc = make_float4(0.f, 0.f, 0.f, 0.f);
    float z = 0.f;

    for (int cb = b; cb < e; cb += 32) {
        const int n = min(32, e - cb);
        int mysrc = 0;
        if (cb + lane < e) mysrc = __ldg(psrc + cb + lane);

        int i = 0;
        for (; i + 8 <= n; i += 8) {
#pragma unroll
            for (int u = 0; u < 8; u++) {
                const int src = __shfl_sync(0xffffffffu, mysrc, i + u);
                const float s = __ldg(pscore + (size_t)(cb + i + u) * NH + h);
                const float4 v = __ldg((const float4*)(V + (size_t)src * DIM) + lane);
                acc.x = fmaf(v.x, s, acc.x);
                acc.y = fmaf(v.y, s, acc.y);
                acc.z = fmaf(v.z, s, acc.z);
                acc.w = fmaf(v.w, s, acc.w);
                z += s;
            }
        }
        for (; i < n; i++) {
            const int src = __shfl_sync(0xffffffffu, mysrc, i);
            const float s = __ldg(pscore + (size_t)(cb + i) * NH + h);
            const float4 v = __ldg((const float4*)(V + (size_t)src * DIM) + lane);
            acc.x = fmaf(v.x, s, acc.x);
            acc.y = fmaf(v.y, s, acc.y);
            acc.z = fmaf(v.z, s, acc.z);
            acc.w = fmaf(v.w, s, acc.w);
            z += s;
        }
    }
    const float inv = 1.0f / (z + 1e-6f);
    *(float4*)(out + (size_t)node * DIM + lane * 4) =
        make_float4(acc.x * inv, acc.y * inv, acc.z * inv, acc.w * inv);
}

// ---------------- launch --------------------------------------------------------
extern "C" void kernel_launch(void* const* d_in, const int* in_sizes, int n_in,
                              void* d_out, int out_size) {
    const float* h   = (const float*)d_in[0];
    const float* ea  = (const float*)d_in[1];
    const float* WQ  = (const float*)d_in[2];
    const float* WK  = (const float*)d_in[3];
    const float* WV  = (const float*)d_in[4];
    const float* WE  = (const float*)d_in[5];
    const void*  eix = d_in[6];
    float* out = (float*)d_out;

    void *qp, *kp, *vp, *cntp, *basep, *psrcp, *pdstp, *pinvp, *pscorep;
    cudaGetSymbolAddress(&qp,      g_Q);
    cudaGetSymbolAddress(&kp,      g_K);
    cudaGetSymbolAddress(&vp,      g_V);
    cudaGetSymbolAddress(&cntp,    g_cnt);
    cudaGetSymbolAddress(&basep,   g_base);
    cudaGetSymbolAddress(&psrcp,   g_psrc);
    cudaGetSymbolAddress(&pdstp,   g_pdst);
    cudaGetSymbolAddress(&pinvp,   g_pinv);
    cudaGetSymbolAddress(&pscorep, g_pscore);

    detect_idx_kernel<<<1, 1>>>(eix);

    // CSR build
    cudaMemsetAsync(cntp, 0, N_NODES * sizeof(int));
    hist_kernel<<<(N_EDGES + 255) / 256, 256>>>(eix, (int*)cntp);
    scan_kernel<<<1, 1024>>>((const int*)cntp, (int*)basep);
    cudaMemsetAsync(cntp, 0, N_NODES * sizeof(int));
    convert_kernel<<<(N_EDGES + 255) / 256, 256>>>(
        eix, (const int*)basep, (int*)cntp,
        (int*)psrcp, (int*)pdstp, (int*)pinvp);

    // node projections (3 GEMMs in one launch)
    dim3 gN((N_NODES + BM - 1) / BM, 3);
    sgemm3_kernel<<<gN, 256>>>(h, WQ, WK, WV, (float*)qp, (float*)kp, (float*)vp,
                               N_NODES);

    // fused persistent fp16 edge GEMM + score (2 CTAs/SM)
    const int smem_bytes = (64 * PADB + 64 * PADA + 64 * PAD) * 4;   // 86016
    cudaFuncSetAttribute(fused_edge_kernel,
                         cudaFuncAttributeMaxDynamicSharedMemorySize, smem_bytes);
    fused_edge_kernel<<<NPER, 256, smem_bytes>>>(
        ea, WE, (const float*)qp, (const float*)kp,
        (const int*)psrcp, (const int*)pdstp, (const int*)pinvp,
        (float*)pscorep);

    // gather + normalize (one warp per node)
    gather_kernel<<<(N_NODES * 32 + 255) / 256, 256>>>(
        (const int*)basep, (const int*)psrcp, (const float*)pscorep,
        (const float*)vp, out);
}